// round 7
// baseline (speedup 1.0000x reference)
#include <cuda_runtime.h>
#include <cstdint>

// CausalConv1d: y[b,l,d] = bias[d] + sum_{k=0..3} x[b, l-3+k, d] * w[d,0,k]
// x: (B=8, L=4096, D=1024) fp32, D innermost. w: (D,1,4). b: (D,). Out: (B,L,D).
//
// HBM-bound. In-flight bytes moved from registers to SMEM: 4-stage x 32KB
// TMA (cp.async.bulk) ring per block, mbarrier-paced. Consumers read each
// SMEM row once (LDS.128), keep a 3-row register window, STG.128 results.
// 512 blocks x 64 rows exact tiling, 1 block/SM, 3.46 waves (spread smoothing).

#define CC_B 8
#define CC_L 4096
#define CC_D 1024
#define CC_K 4
#define CC_DV 256                        // float4 lanes over D
#define CC_ROW_BYTES (CC_D * 4)          // 4096 B per row
#define CC_LC 64                         // rows per block
#define CC_TILE 8                        // rows per stage
#define CC_NTILE (CC_LC / CC_TILE)       // 8
#define CC_STAGES 4
#define CC_STAGE_BYTES (CC_TILE * CC_ROW_BYTES)   // 32768
#define CC_NCHUNK (CC_L / CC_LC)         // 64
#define CC_GRID (CC_B * CC_NCHUNK)       // 512
#define CC_SMEM_DATA (CC_STAGES * CC_STAGE_BYTES) // 131072
#define CC_SMEM_TOTAL (CC_SMEM_DATA + CC_STAGES * 8)

__device__ __forceinline__ void mbar_init(uint32_t addr, uint32_t count) {
    asm volatile("mbarrier.init.shared.b64 [%0], %1;" :: "r"(addr), "r"(count) : "memory");
}
__device__ __forceinline__ void mbar_expect_tx(uint32_t addr, uint32_t bytes) {
    asm volatile("mbarrier.arrive.expect_tx.shared.b64 _, [%0], %1;"
                 :: "r"(addr), "r"(bytes) : "memory");
}
__device__ __forceinline__ void mbar_wait(uint32_t addr, uint32_t parity) {
    asm volatile(
        "{\n\t.reg .pred P;\n"
        "W_%=:\n\t"
        "mbarrier.try_wait.parity.acquire.cta.shared::cta.b64 P, [%0], %1, 0x989680;\n\t"
        "@!P bra W_%=;\n\t}"
        :: "r"(addr), "r"(parity) : "memory");
}
__device__ __forceinline__ void tma_bulk_g2s(uint32_t dst_smem, const void* src_gmem,
                                             uint32_t bytes, uint32_t mbar) {
    asm volatile(
        "cp.async.bulk.shared::cluster.global.mbarrier::complete_tx::bytes [%0], [%1], %2, [%3];"
        :: "r"(dst_smem), "l"(src_gmem), "r"(bytes), "r"(mbar) : "memory");
}

__global__ __launch_bounds__(CC_DV, 1)
void causal_conv1d_kernel(const float* __restrict__ xf,
                          const float* __restrict__ w,
                          const float4* __restrict__ bias,
                          float4*       __restrict__ y)
{
    extern __shared__ char smem[];
    const uint32_t smem_u32 = (uint32_t)__cvta_generic_to_shared(smem);
    const uint32_t data_base = smem_u32;
    const uint32_t mbar_base = smem_u32 + CC_SMEM_DATA;

    const int d4 = threadIdx.x;          // 0..255
    const int d0 = d4 * 4;
    const int chunk = blockIdx.x & (CC_NCHUNK - 1);
    const int b = blockIdx.x >> 6;
    const int l0 = chunk * CC_LC;

    // Init mbarriers, fence async proxy, kick off the first 4 stages.
    if (threadIdx.x == 0) {
        #pragma unroll
        for (int s = 0; s < CC_STAGES; s++) mbar_init(mbar_base + s * 8, 1);
    }
    __syncthreads();
    asm volatile("fence.proxy.async.shared::cta;" ::: "memory");

    const char* xg = (const char*)xf + (size_t)(b * CC_L + l0) * CC_ROW_BYTES;
    if (threadIdx.x == 0) {
        #pragma unroll
        for (int s = 0; s < CC_STAGES; s++) {
            mbar_expect_tx(mbar_base + s * 8, CC_STAGE_BYTES);
            tma_bulk_g2s(data_base + s * CC_STAGE_BYTES,
                         xg + (size_t)s * CC_STAGE_BYTES,
                         CC_STAGE_BYTES, mbar_base + s * 8);
        }
    }

    // Per-lane weights regrouped by tap: wk[k].{x,y,z,w} = tap k, chans d0..d0+3.
    float4 wk0, wk1, wk2, wk3;
    wk0.x = w[(d0 + 0) * CC_K + 0]; wk0.y = w[(d0 + 1) * CC_K + 0];
    wk0.z = w[(d0 + 2) * CC_K + 0]; wk0.w = w[(d0 + 3) * CC_K + 0];
    wk1.x = w[(d0 + 0) * CC_K + 1]; wk1.y = w[(d0 + 1) * CC_K + 1];
    wk1.z = w[(d0 + 2) * CC_K + 1]; wk1.w = w[(d0 + 3) * CC_K + 1];
    wk2.x = w[(d0 + 0) * CC_K + 2]; wk2.y = w[(d0 + 1) * CC_K + 2];
    wk2.z = w[(d0 + 2) * CC_K + 2]; wk2.w = w[(d0 + 3) * CC_K + 2];
    wk3.x = w[(d0 + 0) * CC_K + 3]; wk3.y = w[(d0 + 1) * CC_K + 3];
    wk3.z = w[(d0 + 2) * CC_K + 3]; wk3.w = w[(d0 + 3) * CC_K + 3];
    const float4 bv = bias[d4];

    // Halo window from gmem (previous block's rows), zeros at sequence start.
    const float4* x4 = (const float4*)xf;
    const size_t rowbase = (size_t)(b * CC_L + l0) * CC_DV + d4;
    float4 wa, wb, wc;                   // x[l0-3], x[l0-2], x[l0-1]
    if (l0 == 0) {
        wa = make_float4(0.f, 0.f, 0.f, 0.f); wb = wa; wc = wa;
    } else {
        wa = x4[rowbase - 3 * CC_DV];
        wb = x4[rowbase - 2 * CC_DV];
        wc = x4[rowbase - 1 * CC_DV];
    }

    const char* smem_gp = smem;          // generic pointer for LDS

    #pragma unroll
    for (int t = 0; t < CC_NTILE; t++) {
        const int slot = t & (CC_STAGES - 1);
        const uint32_t phase = (t >> 2) & 1;

        mbar_wait(mbar_base + slot * 8, phase);

        // Batch-read the 8 rows of this stage from SMEM.
        const char* sp = smem_gp + slot * CC_STAGE_BYTES + d4 * 16;
        float4 r[CC_TILE];
        #pragma unroll
        for (int i = 0; i < CC_TILE; i++)
            r[i] = *(const float4*)(sp + i * CC_ROW_BYTES);

        // Compute + store 8 rows using the 3-row register window.
        const size_t ob = rowbase + (size_t)t * CC_TILE * CC_DV;
        #pragma unroll
        for (int i = 0; i < CC_TILE; i++) {
            const float4 a3 = (i >= 3) ? r[i - 3] : (i == 0 ? wa : (i == 1 ? wb : wc));
            const float4 a2 = (i >= 2) ? r[i - 2] : (i == 0 ? wb : wc);
            const float4 a1 = (i >= 1) ? r[i - 1] : wc;
            const float4 a0 = r[i];
            float4 o;
            o.x = fmaf(wk0.x, a3.x, fmaf(wk1.x, a2.x, fmaf(wk2.x, a1.x, fmaf(wk3.x, a0.x, bv.x))));
            o.y = fmaf(wk0.y, a3.y, fmaf(wk1.y, a2.y, fmaf(wk2.y, a1.y, fmaf(wk3.y, a0.y, bv.y))));
            o.z = fmaf(wk0.z, a3.z, fmaf(wk1.z, a2.z, fmaf(wk2.z, a1.z, fmaf(wk3.z, a0.z, bv.z))));
            o.w = fmaf(wk0.w, a3.w, fmaf(wk1.w, a2.w, fmaf(wk2.w, a1.w, fmaf(wk3.w, a0.w, bv.w))));
            y[ob + (size_t)i * CC_DV] = o;
        }

        // Roll window into next tile.
        wa = r[CC_TILE - 3];
        wb = r[CC_TILE - 2];
        wc = r[CC_TILE - 1];

        // All threads done with this slot -> refill it with stage t+4.
        __syncthreads();
        if (threadIdx.x == 0 && (t + CC_STAGES) < CC_NTILE) {
            mbar_expect_tx(mbar_base + slot * 8, CC_STAGE_BYTES);
            tma_bulk_g2s(data_base + slot * CC_STAGE_BYTES,
                         xg + (size_t)(t + CC_STAGES) * CC_STAGE_BYTES,
                         CC_STAGE_BYTES, mbar_base + slot * 8);
        }
    }
}

extern "C" void kernel_launch(void* const* d_in, const int* in_sizes, int n_in,
                              void* d_out, int out_size)
{
    (void)in_sizes; (void)n_in; (void)out_size;
    const float*  x    = (const float*)d_in[0];
    const float*  w    = (const float*)d_in[1];
    const float4* bias = (const float4*)d_in[2];
    float4*       y    = (float4*)d_out;

    cudaFuncSetAttribute(causal_conv1d_kernel,
                         cudaFuncAttributeMaxDynamicSharedMemorySize, CC_SMEM_TOTAL);
    causal_conv1d_kernel<<<CC_GRID, CC_DV, CC_SMEM_TOTAL>>>(x, w, bias, y);
}

// round 8
// speedup vs baseline: 1.0007x; 1.0007x over previous
#include <cuda_runtime.h>
#include <cstdint>

// CausalConv1d: y[b,l,d] = bias[d] + sum_{k=0..3} x[b, l-3+k, d] * w[d,0,k]
// x: (B=8, L=4096, D=1024) fp32, D innermost. w: (D,1,4). b: (D,). Out: (B,L,D).
//
// HBM-bound; limiter is DRAM read/write turnaround on fine interleave.
// Fix: ALL traffic in 32KB bulk bursts. Load: 4-stage cp.async.bulk G2S ring
// (mbarrier). Store: compute -> STS into 2-stage out ring -> cp.async.bulk
// S2G (bulk_group). 512 blocks x 64 rows, 1 block/SM, 192KB SMEM.

#define CC_B 8
#define CC_L 4096
#define CC_D 1024
#define CC_K 4
#define CC_DV 256                         // float4 lanes over D
#define CC_ROW_BYTES (CC_D * 4)           // 4096
#define CC_LC 64                          // rows per block
#define CC_TILE 8                         // rows per stage
#define CC_NTILE (CC_LC / CC_TILE)        // 8
#define CC_IN_STAGES 4
#define CC_OUT_STAGES 2
#define CC_STAGE_BYTES (CC_TILE * CC_ROW_BYTES)     // 32768
#define CC_NCHUNK (CC_L / CC_LC)          // 64
#define CC_GRID (CC_B * CC_NCHUNK)        // 512
#define CC_SMEM_IN  (CC_IN_STAGES * CC_STAGE_BYTES)   // 131072
#define CC_SMEM_OUT (CC_OUT_STAGES * CC_STAGE_BYTES)  // 65536
#define CC_SMEM_TOTAL (CC_SMEM_IN + CC_SMEM_OUT + 64)

__device__ __forceinline__ void mbar_init(uint32_t addr, uint32_t count) {
    asm volatile("mbarrier.init.shared.b64 [%0], %1;" :: "r"(addr), "r"(count) : "memory");
}
__device__ __forceinline__ void mbar_expect_tx(uint32_t addr, uint32_t bytes) {
    asm volatile("mbarrier.arrive.expect_tx.shared.b64 _, [%0], %1;"
                 :: "r"(addr), "r"(bytes) : "memory");
}
__device__ __forceinline__ void mbar_wait(uint32_t addr, uint32_t parity) {
    asm volatile(
        "{\n\t.reg .pred P;\n"
        "W_%=:\n\t"
        "mbarrier.try_wait.parity.acquire.cta.shared::cta.b64 P, [%0], %1, 0x989680;\n\t"
        "@!P bra W_%=;\n\t}"
        :: "r"(addr), "r"(parity) : "memory");
}
__device__ __forceinline__ void tma_bulk_g2s(uint32_t dst_smem, const void* src_gmem,
                                             uint32_t bytes, uint32_t mbar) {
    asm volatile(
        "cp.async.bulk.shared::cluster.global.mbarrier::complete_tx::bytes [%0], [%1], %2, [%3];"
        :: "r"(dst_smem), "l"(src_gmem), "r"(bytes), "r"(mbar) : "memory");
}
__device__ __forceinline__ void tma_bulk_s2g(void* dst_gmem, uint32_t src_smem,
                                             uint32_t bytes) {
    asm volatile("cp.async.bulk.global.shared::cta.bulk_group [%0], [%1], %2;"
                 :: "l"(dst_gmem), "r"(src_smem), "r"(bytes) : "memory");
}
__device__ __forceinline__ void tma_commit_group() {
    asm volatile("cp.async.bulk.commit_group;" ::: "memory");
}
template <int N>
__device__ __forceinline__ void tma_wait_group() {
    asm volatile("cp.async.bulk.wait_group %0;" :: "n"(N) : "memory");
}

__global__ __launch_bounds__(CC_DV, 1)
void causal_conv1d_kernel(const float* __restrict__ xf,
                          const float* __restrict__ w,
                          const float4* __restrict__ bias,
                          float*       __restrict__ yf)
{
    extern __shared__ char smem[];
    const uint32_t smem_u32 = (uint32_t)__cvta_generic_to_shared(smem);
    const uint32_t in_base   = smem_u32;
    const uint32_t out_base  = smem_u32 + CC_SMEM_IN;
    const uint32_t mbar_base = smem_u32 + CC_SMEM_IN + CC_SMEM_OUT;

    const int d4 = threadIdx.x;           // 0..255
    const int d0 = d4 * 4;
    const int chunk = blockIdx.x & (CC_NCHUNK - 1);
    const int b = blockIdx.x >> 6;
    const int l0 = chunk * CC_LC;

    if (threadIdx.x == 0) {
        #pragma unroll
        for (int s = 0; s < CC_IN_STAGES; s++) mbar_init(mbar_base + s * 8, 1);
    }
    __syncthreads();
    asm volatile("fence.proxy.async.shared::cta;" ::: "memory");

    const char* xg = (const char*)xf + (size_t)(b * CC_L + l0) * CC_ROW_BYTES;
    char*       yg = (char*)yf + (size_t)(b * CC_L + l0) * CC_ROW_BYTES;

    if (threadIdx.x == 0) {
        #pragma unroll
        for (int s = 0; s < CC_IN_STAGES; s++) {
            mbar_expect_tx(mbar_base + s * 8, CC_STAGE_BYTES);
            tma_bulk_g2s(in_base + s * CC_STAGE_BYTES,
                         xg + (size_t)s * CC_STAGE_BYTES,
                         CC_STAGE_BYTES, mbar_base + s * 8);
        }
    }

    // Per-lane weights regrouped by tap.
    float4 wk0, wk1, wk2, wk3;
    wk0.x = w[(d0 + 0) * CC_K + 0]; wk0.y = w[(d0 + 1) * CC_K + 0];
    wk0.z = w[(d0 + 2) * CC_K + 0]; wk0.w = w[(d0 + 3) * CC_K + 0];
    wk1.x = w[(d0 + 0) * CC_K + 1]; wk1.y = w[(d0 + 1) * CC_K + 1];
    wk1.z = w[(d0 + 2) * CC_K + 1]; wk1.w = w[(d0 + 3) * CC_K + 1];
    wk2.x = w[(d0 + 0) * CC_K + 2]; wk2.y = w[(d0 + 1) * CC_K + 2];
    wk2.z = w[(d0 + 2) * CC_K + 2]; wk2.w = w[(d0 + 3) * CC_K + 2];
    wk3.x = w[(d0 + 0) * CC_K + 3]; wk3.y = w[(d0 + 1) * CC_K + 3];
    wk3.z = w[(d0 + 2) * CC_K + 3]; wk3.w = w[(d0 + 3) * CC_K + 3];
    const float4 bv = bias[d4];

    // Halo window (x[l0-3..l0-1]) from gmem; zeros at sequence start.
    const float4* x4 = (const float4*)xf;
    const size_t rowbase = (size_t)(b * CC_L + l0) * CC_DV + d4;
    float4 ha, hb, hc;
    if (l0 == 0) {
        ha = make_float4(0.f, 0.f, 0.f, 0.f); hb = ha; hc = ha;
    } else {
        ha = x4[rowbase - 3 * CC_DV];
        hb = x4[rowbase - 2 * CC_DV];
        hc = x4[rowbase - 1 * CC_DV];
    }

    const char* smem_gp = smem;

    #pragma unroll
    for (int t = 0; t < CC_NTILE; t++) {
        const int in_slot  = t & (CC_IN_STAGES - 1);
        const int out_slot = t & (CC_OUT_STAGES - 1);
        const uint32_t phase = (t >> 2) & 1;

        mbar_wait(mbar_base + in_slot * 8, phase);

        // Batch-read the 8 input rows of this stage (LDS.128).
        const char* sp = smem_gp + in_slot * CC_STAGE_BYTES + d4 * 16;
        float4 r[CC_TILE];
        #pragma unroll
        for (int i = 0; i < CC_TILE; i++)
            r[i] = *(const float4*)(sp + i * CC_ROW_BYTES);

        // Out slot must be free: the S2G store issued 2 tiles ago has drained.
        if (t >= CC_OUT_STAGES) {
            if (threadIdx.x == 0) tma_wait_group<1>();
            __syncthreads();
        }

        // Compute + STS 8 rows into the out slot.
        char* op = smem + (CC_SMEM_IN + out_slot * CC_STAGE_BYTES) + d4 * 16;
        #pragma unroll
        for (int i = 0; i < CC_TILE; i++) {
            const float4 a3 = (i >= 3) ? r[i - 3] : (i == 0 ? ha : (i == 1 ? hb : hc));
            const float4 a2 = (i >= 2) ? r[i - 2] : (i == 0 ? hb : hc);
            const float4 a1 = (i >= 1) ? r[i - 1] : hc;
            const float4 a0 = r[i];
            float4 o;
            o.x = fmaf(wk0.x, a3.x, fmaf(wk1.x, a2.x, fmaf(wk2.x, a1.x, fmaf(wk3.x, a0.x, bv.x))));
            o.y = fmaf(wk0.y, a3.y, fmaf(wk1.y, a2.y, fmaf(wk2.y, a1.y, fmaf(wk3.y, a0.y, bv.y))));
            o.z = fmaf(wk0.z, a3.z, fmaf(wk1.z, a2.z, fmaf(wk2.z, a1.z, fmaf(wk3.z, a0.z, bv.z))));
            o.w = fmaf(wk0.w, a3.w, fmaf(wk1.w, a2.w, fmaf(wk2.w, a1.w, fmaf(wk3.w, a0.w, bv.w))));
            *(float4*)(op + i * CC_ROW_BYTES) = o;
        }

        // Roll window.
        ha = r[CC_TILE - 3];
        hb = r[CC_TILE - 2];
        hc = r[CC_TILE - 1];

        __syncthreads();   // STS complete block-wide; LDS of in_slot done too.

        if (threadIdx.x == 0) {
            // Bulk-store this stage's output.
            asm volatile("fence.proxy.async.shared::cta;" ::: "memory");
            tma_bulk_s2g(yg + (size_t)t * CC_STAGE_BYTES,
                         out_base + out_slot * CC_STAGE_BYTES, CC_STAGE_BYTES);
            tma_commit_group();
            // Refill the in slot with stage t+4.
            if (t + CC_IN_STAGES < CC_NTILE) {
                mbar_expect_tx(mbar_base + in_slot * 8, CC_STAGE_BYTES);
                tma_bulk_g2s(in_base + in_slot * CC_STAGE_BYTES,
                             xg + (size_t)(t + CC_IN_STAGES) * CC_STAGE_BYTES,
                             CC_STAGE_BYTES, mbar_base + in_slot * 8);
            }
        }
    }

    // Drain outstanding bulk stores before CTA exit (SMEM reuse safety).
    if (threadIdx.x == 0) tma_wait_group<0>();
    __syncthreads();
}

extern "C" void kernel_launch(void* const* d_in, const int* in_sizes, int n_in,
                              void* d_out, int out_size)
{
    (void)in_sizes; (void)n_in; (void)out_size;
    const float*  x    = (const float*)d_in[0];
    const float*  w    = (const float*)d_in[1];
    const float4* bias = (const float4*)d_in[2];
    float*        y    = (float*)d_out;

    cudaFuncSetAttribute(causal_conv1d_kernel,
                         cudaFuncAttributeMaxDynamicSharedMemorySize, CC_SMEM_TOTAL);
    causal_conv1d_kernel<<<CC_GRID, CC_DV, CC_SMEM_TOTAL>>>(x, w, bias, y);
}